// round 10
// baseline (speedup 1.0000x reference)
#include <cuda_runtime.h>
#include <cstdint>
#include <cstddef>

#define B_ 8
#define S_ 2048
#define D_ 1024
#define MTOK (B_ * S_)
#define NELEM ((size_t)MTOK * D_)
#define SB_ ((long long)S_ * D_)
#define SL_ ((long long)S_ * S_)

// ---- static device scratch (allocation-free rule) ----
__device__ __align__(16) float g_X[3 * NELEM];             // tf32-rounded inputs
__device__ __align__(16) float g_P[3 * NELEM];             // projected Q,K,V
__device__ __align__(16) float g_L[(size_t)B_ * S_ * S_];  // logits / weights
__device__ __align__(16) float g_VT[(size_t)B_ * D_ * S_]; // V^T per batch
__device__ __align__(16) float g_WT[(size_t)D_ * D_];      // W^T

// ---- helpers ----
__device__ __forceinline__ float tf32r(float x) {
    uint32_t u;
    asm("cvt.rna.tf32.f32 %0, %1;" : "=r"(u) : "f"(x));
    return __uint_as_float(u);
}
__device__ __forceinline__ uint32_t smem_u32(const void* p) {
    uint32_t a;
    asm("{ .reg .u64 t; cvta.to.shared.u64 t, %1; cvt.u32.u64 %0, t; }" : "=r"(a) : "l"(p));
    return a;
}
__device__ __forceinline__ void cp16(uint32_t s, const void* g) {
    asm volatile("cp.async.cg.shared.global [%0], [%1], 16;" :: "r"(s), "l"(g) : "memory");
}
__device__ __forceinline__ void mma_tf32(float* c, const uint32_t* a, const uint32_t* b) {
    asm volatile(
        "mma.sync.aligned.m16n8k8.row.col.f32.tf32.tf32.f32 "
        "{%0,%1,%2,%3}, {%4,%5,%6,%7}, {%8,%9}, {%0,%1,%2,%3};"
        : "+f"(c[0]), "+f"(c[1]), "+f"(c[2]), "+f"(c[3])
        : "r"(a[0]), "r"(a[1]), "r"(a[2]), "r"(a[3]), "r"(b[0]), "r"(b[1]));
}

// ---- tf32 GEMM: C[M,N] = scale*(A @ B^T)(+bias). CTA tile 256x128x32,
// ---- 8 warps as 4Mx2N, warp tile 64x64, 3-stage cp.async pipeline. ----
#define BM 256
#define BN 128
#define BKF 32
#define LDA 36                        // 32 + 4 pad floats, rows stay 16B-aligned
#define ASTG (BM * LDA)               // 9216 floats: A stage
#define BSTG (BN * LDA)               // 4608 floats: B stage
#define STGF (ASTG + BSTG)            // 13824 floats per stage
#define GSMEM_FLOATS (128 + 3 * STGF)
#define GSMEM_BYTES (GSMEM_FLOATS * 4)  // ~166 KB

__device__ __forceinline__ void load_tileA(const float* __restrict__ src, int ld,
                                           int row0, int k0, float* st, int tid) {
#pragma unroll
    for (int i = 0; i < 8; i++) {                 // 2048 16B chunks
        int idx = i * 256 + tid;
        int r = idx >> 3, c = idx & 7;
        cp16(smem_u32(st + r * LDA + c * 4),
             src + (size_t)(row0 + r) * ld + (k0 + c * 4));
    }
}
__device__ __forceinline__ void load_tileB(const float* __restrict__ src, int ld,
                                           int row0, int k0, float* st, int tid) {
#pragma unroll
    for (int i = 0; i < 4; i++) {                 // 1024 16B chunks
        int idx = i * 256 + tid;
        int r = idx >> 3, c = idx & 7;
        cp16(smem_u32(st + r * LDA + c * 4),
             src + (size_t)(row0 + r) * ld + (k0 + c * 4));
    }
}

__global__ void __launch_bounds__(256, 1) gemm_tf32(
    const float* __restrict__ A, const float* __restrict__ Bm,
    float* __restrict__ C, const float* __restrict__ bias,
    float scale, int round_out, int K, int N,
    long long sA, long long sB, long long sC)
{
    extern __shared__ float sm[];
    float* bias_s = sm;
    float* tiles  = sm + 128;

    const int tid = threadIdx.x, wid = tid >> 5, lane = tid & 31;
    const int g = lane >> 2, t = lane & 3;
    const int wm = (wid & 3) * 64;       // warp M offset (4 warps over 256)
    const int wn = (wid >> 2) * 64;      // warp N offset (2 warps over 128)
    const int m0 = blockIdx.x * BM, n0 = blockIdx.y * BN;

    A  += (long long)blockIdx.z * sA;
    Bm += (long long)blockIdx.z * sB;
    C  += (long long)blockIdx.z * sC;

    if (bias && tid < 128) bias_s[tid] = bias[n0 + tid];

    const int nK = K >> 5;

#pragma unroll
    for (int p = 0; p < 2; p++) {
        load_tileA(A,  K, m0, p * BKF, tiles + p * STGF, tid);
        load_tileB(Bm, K, n0, p * BKF, tiles + p * STGF + ASTG, tid);
        asm volatile("cp.async.commit_group;" ::: "memory");
    }

    float acc[4][8][4];
#pragma unroll
    for (int mi = 0; mi < 4; mi++)
#pragma unroll
        for (int nj = 0; nj < 8; nj++)
#pragma unroll
            for (int q = 0; q < 4; q++) acc[mi][nj][q] = 0.0f;

    for (int s = 0; s < nK; s++) {
        __syncthreads();                       // compute(s-1) done before overwrite
        if (s + 2 < nK) {
            float* st = tiles + ((s + 2) % 3) * STGF;
            load_tileA(A,  K, m0, (s + 2) * BKF, st, tid);
            load_tileB(Bm, K, n0, (s + 2) * BKF, st + ASTG, tid);
        }
        asm volatile("cp.async.commit_group;" ::: "memory");
        asm volatile("cp.async.wait_group 2;" ::: "memory");   // stage s resident
        __syncthreads();

        const float* As = tiles + (s % 3) * STGF;
        const float* Bs = As + ASTG;

#pragma unroll
        for (int ks = 0; ks < 4; ks++) {
            const int kb = ks * 8;
            uint32_t a[4][4], b[8][2];
#pragma unroll
            for (int mi = 0; mi < 4; mi++) {
                const float* ap = As + (wm + mi * 16 + g) * LDA + kb + t;
                a[mi][0] = __float_as_uint(ap[0]);
                a[mi][1] = __float_as_uint(ap[8 * LDA]);
                a[mi][2] = __float_as_uint(ap[4]);
                a[mi][3] = __float_as_uint(ap[8 * LDA + 4]);
            }
#pragma unroll
            for (int nj = 0; nj < 8; nj++) {
                const float* bp = Bs + (wn + nj * 8 + g) * LDA + kb + t;
                b[nj][0] = __float_as_uint(bp[0]);
                b[nj][1] = __float_as_uint(bp[4]);
            }
#pragma unroll
            for (int mi = 0; mi < 4; mi++)
#pragma unroll
                for (int nj = 0; nj < 8; nj++)
                    mma_tf32(acc[mi][nj], a[mi], b[nj]);
        }
    }

    __syncthreads();
    const bool hb = (bias != nullptr);
#pragma unroll
    for (int mi = 0; mi < 4; mi++) {
#pragma unroll
        for (int nj = 0; nj < 8; nj++) {
            int row = m0 + wm + mi * 16 + g;
            int col = n0 + wn + nj * 8 + 2 * t;
            float b0 = hb ? bias_s[wn + nj * 8 + 2 * t]     : 0.0f;
            float b1 = hb ? bias_s[wn + nj * 8 + 2 * t + 1] : 0.0f;
            float2 v0, v1;
            v0.x = acc[mi][nj][0] * scale + b0;
            v0.y = acc[mi][nj][1] * scale + b1;
            v1.x = acc[mi][nj][2] * scale + b0;
            v1.y = acc[mi][nj][3] * scale + b1;
            if (round_out) {
                v0.x = tf32r(v0.x); v0.y = tf32r(v0.y);
                v1.x = tf32r(v1.x); v1.y = tf32r(v1.y);
            }
            *(float2*)(C + (size_t)row * N + col)       = v0;
            *(float2*)(C + (size_t)(row + 8) * N + col) = v1;
        }
    }
}

// ---- tf32-round copy ----
__global__ void __launch_bounds__(256) round_copy(const float* __restrict__ in,
                                                  float* __restrict__ out) {
    size_t i = (size_t)blockIdx.x * blockDim.x + threadIdx.x;
    float4 v = ((const float4*)in)[i];
    v.x = tf32r(v.x); v.y = tf32r(v.y); v.z = tf32r(v.z); v.w = tf32r(v.w);
    ((float4*)out)[i] = v;
}

// ---- tiled transpose with tf32 rounding: out[c][r] = rna(in[r][c]) ----
__global__ void __launch_bounds__(256) transpose_round(
    const float* __restrict__ in, float* __restrict__ out,
    int rows, int cols, long long sIn, long long sOut)
{
    __shared__ float tbuf[32][33];
    in  += (long long)blockIdx.z * sIn;
    out += (long long)blockIdx.z * sOut;
    int c0 = blockIdx.x * 32, r0 = blockIdx.y * 32;
    int x = threadIdx.x & 31, y = threadIdx.x >> 5;
#pragma unroll
    for (int i = 0; i < 32; i += 8)
        tbuf[y + i][x] = in[(size_t)(r0 + y + i) * cols + c0 + x];
    __syncthreads();
#pragma unroll
    for (int i = 0; i < 32; i += 8)
        out[(size_t)(c0 + y + i) * rows + r0 + x] = tf32r(tbuf[x][y + i]);
}

// ---- row softmax (2048 cols, 256 threads/row), tf32-rounded store ----
__global__ void __launch_bounds__(256) softmax_rows(float* __restrict__ P) {
    float* r = P + (size_t)blockIdx.x * 2048;
    const int tid = threadIdx.x, lane = tid & 31, wid = tid >> 5;
    __shared__ float red[8];

    float4 a = *(const float4*)(r + tid * 4);
    float4 b = *(const float4*)(r + 1024 + tid * 4);

    float m = fmaxf(fmaxf(fmaxf(a.x, a.y), fmaxf(a.z, a.w)),
                    fmaxf(fmaxf(b.x, b.y), fmaxf(b.z, b.w)));
#pragma unroll
    for (int o = 16; o; o >>= 1) m = fmaxf(m, __shfl_xor_sync(~0u, m, o));
    if (lane == 0) red[wid] = m;
    __syncthreads();
    m = red[0];
#pragma unroll
    for (int i = 1; i < 8; i++) m = fmaxf(m, red[i]);
    __syncthreads();

    a.x = expf(a.x - m); a.y = expf(a.y - m); a.z = expf(a.z - m); a.w = expf(a.w - m);
    b.x = expf(b.x - m); b.y = expf(b.y - m); b.z = expf(b.z - m); b.w = expf(b.w - m);
    float s = a.x + a.y + a.z + a.w + b.x + b.y + b.z + b.w;
#pragma unroll
    for (int o = 16; o; o >>= 1) s += __shfl_xor_sync(~0u, s, o);
    if (lane == 0) red[wid] = s;
    __syncthreads();
    s = red[0];
#pragma unroll
    for (int i = 1; i < 8; i++) s += red[i];
    float inv = 1.0f / s;

    a.x = tf32r(a.x * inv); a.y = tf32r(a.y * inv); a.z = tf32r(a.z * inv); a.w = tf32r(a.w * inv);
    b.x = tf32r(b.x * inv); b.y = tf32r(b.y * inv); b.z = tf32r(b.z * inv); b.w = tf32r(b.w * inv);
    *(float4*)(r + tid * 4) = a;
    *(float4*)(r + 1024 + tid * 4) = b;
}

// ---- host launcher ----
extern "C" void kernel_launch(void* const* d_in, const int* in_sizes, int n_in,
                              void* d_out, int out_size) {
    const float* q  = (const float*)d_in[0];
    const float* k  = (const float*)d_in[1];
    const float* v  = (const float*)d_in[2];
    const float* Wq = (const float*)d_in[3];
    const float* bq = (const float*)d_in[4];
    float* out = (float*)d_out;

    float *pX, *pP, *pL, *pVT, *pWT;
    cudaGetSymbolAddress((void**)&pX,  g_X);
    cudaGetSymbolAddress((void**)&pP,  g_P);
    cudaGetSymbolAddress((void**)&pL,  g_L);
    cudaGetSymbolAddress((void**)&pVT, g_VT);
    cudaGetSymbolAddress((void**)&pWT, g_WT);

    cudaFuncSetAttribute(gemm_tf32, cudaFuncAttributeMaxDynamicSharedMemorySize, GSMEM_BYTES);

    // 1) round inputs to tf32-exact fp32
    round_copy<<<16384, 256>>>(q, pX);
    round_copy<<<16384, 256>>>(k, pX + NELEM);
    round_copy<<<16384, 256>>>(v, pX + 2 * NELEM);
    // 2) W^T (K-major B operand), rounded
    transpose_round<<<dim3(32, 32, 1), 256>>>(Wq, pWT, D_, D_, 0, 0);
    // 3) fused projections: [3*16384,1024] = X @ W + b, tf32-rounded outputs
    gemm_tf32<<<dim3(192, 8, 1), 256, GSMEM_BYTES>>>(
        pX, pWT, pP, bq, 1.0f, 1, D_, D_, 0, 0, 0);
    // 4) logits = Q @ K^T / 32
    gemm_tf32<<<dim3(8, 16, 8), 256, GSMEM_BYTES>>>(
        pP, pP + NELEM, pL, nullptr, 0.03125f, 0, D_, S_, SB_, SB_, SL_);
    // 5) softmax rows (tf32-rounded weights)
    softmax_rows<<<B_ * S_, 256>>>(pL);
    // 6) V^T per batch (rounded)
    transpose_round<<<dim3(32, 64, 8), 256>>>(pP + 2 * NELEM, pVT, S_, D_, SB_, SB_);
    // 7) out = weights @ V
    gemm_tf32<<<dim3(8, 8, 8), 256, GSMEM_BYTES>>>(
        pL, pVT, out, nullptr, 1.0f, 0, S_, D_, SL_, SB_, SB_);
}

// round 11
// speedup vs baseline: 1.9278x; 1.9278x over previous
#include <cuda_runtime.h>
#include <cuda_fp16.h>
#include <cstdint>
#include <cstddef>

#define B_ 8
#define S_ 2048
#define D_ 1024
#define MTOK (B_ * S_)
#define NELEM ((size_t)MTOK * D_)
#define SB_ ((long long)S_ * D_)
#define SL_ ((long long)S_ * S_)

// ---- static device scratch (allocation-free rule) ----
__device__ __align__(16) __half g_Xh[3 * NELEM];             // fp16-rounded inputs
__device__ __align__(16) __half g_Ph[3 * NELEM];             // projected Q,K,V (half)
__device__ __align__(16) float  g_L[(size_t)B_ * S_ * S_];   // fp32 logits
__device__ __align__(16) __half g_Wt[(size_t)B_ * S_ * S_];  // softmax weights (half)
__device__ __align__(16) __half g_VTh[(size_t)B_ * D_ * S_]; // V^T per batch (half)
__device__ __align__(16) __half g_WTh[(size_t)D_ * D_];      // W^T (half)

// ---- helpers ----
__device__ __forceinline__ uint32_t smem_u32(const void* p) {
    uint32_t a;
    asm("{ .reg .u64 t; cvta.to.shared.u64 t, %1; cvt.u32.u64 %0, t; }" : "=r"(a) : "l"(p));
    return a;
}
__device__ __forceinline__ void cp16(uint32_t s, const void* g) {
    asm volatile("cp.async.cg.shared.global [%0], [%1], 16;" :: "r"(s), "l"(g) : "memory");
}
__device__ __forceinline__ void mma_f16(float* c, const uint32_t* a, const uint32_t* b) {
    asm volatile(
        "mma.sync.aligned.m16n8k16.row.col.f32.f16.f16.f32 "
        "{%0,%1,%2,%3}, {%4,%5,%6,%7}, {%8,%9}, {%0,%1,%2,%3};"
        : "+f"(c[0]), "+f"(c[1]), "+f"(c[2]), "+f"(c[3])
        : "r"(a[0]), "r"(a[1]), "r"(a[2]), "r"(a[3]), "r"(b[0]), "r"(b[1]));
}

// ---- fp16 GEMM (fp32 accum): C = scale*(A[M,K] @ B[N,K]^T) (+bias) ----
// CTA tile 128x128, BK=64 halves, 8 warps as 4Mx2N (warp 32x64), 3-stage cp.async.
#define BKH 64
#define LDH 72                         // 64 + 8 pad halves (16B-aligned rows)
#define ASTGH (128 * LDH)              // 9216 halves per operand stage
#define STGH (2 * ASTGH)
#define GSMEM_BYTES (512 + 3 * STGH * 2)   // ~111 KB

__device__ __forceinline__ void load_tile_h(const __half* __restrict__ src, int ld,
                                            int row0, int k0, __half* st, int tid) {
#pragma unroll
    for (int i = 0; i < 4; i++) {              // 1024 chunks of 16B (8 halves)
        int idx = i * 256 + tid;
        int r = idx >> 3, c = idx & 7;
        cp16(smem_u32(st + r * LDH + c * 8),
             src + (size_t)(row0 + r) * ld + (k0 + c * 8));
    }
}

__global__ void __launch_bounds__(256, 2) gemm_fp16(
    const __half* __restrict__ A, const __half* __restrict__ Bm,
    float* __restrict__ Cf, __half* __restrict__ Ch,
    const float* __restrict__ bias,
    float scale, int K, int N,
    long long sA, long long sB, long long sC)
{
    extern __shared__ char smraw[];
    float*  bias_s = (float*)smraw;                 // 128 floats
    __half* tiles  = (__half*)(smraw + 512);

    const int tid = threadIdx.x, wid = tid >> 5, lane = tid & 31;
    const int g = lane >> 2, t = lane & 3;
    const int wm = (wid & 3) * 32;
    const int wn = (wid >> 2) * 64;
    const int m0 = blockIdx.x * 128, n0 = blockIdx.y * 128;

    A  += (long long)blockIdx.z * sA;
    Bm += (long long)blockIdx.z * sB;
    if (Cf) Cf += (long long)blockIdx.z * sC;
    if (Ch) Ch += (long long)blockIdx.z * sC;

    if (bias && tid < 128) bias_s[tid] = bias[n0 + tid];

    const int nK = K >> 6;

#pragma unroll
    for (int p = 0; p < 2; p++) {
        load_tile_h(A,  K, m0, p * BKH, tiles + p * STGH, tid);
        load_tile_h(Bm, K, n0, p * BKH, tiles + p * STGH + ASTGH, tid);
        asm volatile("cp.async.commit_group;" ::: "memory");
    }

    float acc[2][8][4];
#pragma unroll
    for (int mi = 0; mi < 2; mi++)
#pragma unroll
        for (int nj = 0; nj < 8; nj++)
#pragma unroll
            for (int q = 0; q < 4; q++) acc[mi][nj][q] = 0.0f;

    for (int s = 0; s < nK; s++) {
        __syncthreads();
        if (s + 2 < nK) {
            __half* st = tiles + ((s + 2) % 3) * STGH;
            load_tile_h(A,  K, m0, (s + 2) * BKH, st, tid);
            load_tile_h(Bm, K, n0, (s + 2) * BKH, st + ASTGH, tid);
        }
        asm volatile("cp.async.commit_group;" ::: "memory");
        asm volatile("cp.async.wait_group 2;" ::: "memory");
        __syncthreads();

        const __half* As = tiles + (s % 3) * STGH;
        const __half* Bs = As + ASTGH;

#pragma unroll
        for (int ks = 0; ks < 4; ks++) {       // 4 x k16 per 64-half stage
            const int kb = ks * 16;
            uint32_t a[2][4], b[8][2];
#pragma unroll
            for (int mi = 0; mi < 2; mi++) {
                const __half* ap = As + (wm + mi * 16 + g) * LDH + kb + 2 * t;
                a[mi][0] = *(const uint32_t*)(ap);
                a[mi][1] = *(const uint32_t*)(ap + 8 * LDH);
                a[mi][2] = *(const uint32_t*)(ap + 8);
                a[mi][3] = *(const uint32_t*)(ap + 8 * LDH + 8);
            }
#pragma unroll
            for (int nj = 0; nj < 8; nj++) {
                const __half* bp = Bs + (wn + nj * 8 + g) * LDH + kb + 2 * t;
                b[nj][0] = *(const uint32_t*)(bp);
                b[nj][1] = *(const uint32_t*)(bp + 8);
            }
#pragma unroll
            for (int mi = 0; mi < 2; mi++)
#pragma unroll
                for (int nj = 0; nj < 8; nj++)
                    mma_f16(acc[mi][nj], a[mi], b[nj]);
        }
    }

    __syncthreads();
    const bool hb = (bias != nullptr);
#pragma unroll
    for (int mi = 0; mi < 2; mi++) {
#pragma unroll
        for (int nj = 0; nj < 8; nj++) {
            int row = m0 + wm + mi * 16 + g;
            int col = n0 + wn + nj * 8 + 2 * t;
            float b0 = hb ? bias_s[wn + nj * 8 + 2 * t]     : 0.0f;
            float b1 = hb ? bias_s[wn + nj * 8 + 2 * t + 1] : 0.0f;
            float x0 = acc[mi][nj][0] * scale + b0;
            float x1 = acc[mi][nj][1] * scale + b1;
            float x2 = acc[mi][nj][2] * scale + b0;
            float x3 = acc[mi][nj][3] * scale + b1;
            if (Ch) {
                *(__half2*)(Ch + (size_t)row * N + col)       = __floats2half2_rn(x0, x1);
                *(__half2*)(Ch + (size_t)(row + 8) * N + col) = __floats2half2_rn(x2, x3);
            } else {
                *(float2*)(Cf + (size_t)row * N + col)       = make_float2(x0, x1);
                *(float2*)(Cf + (size_t)(row + 8) * N + col) = make_float2(x2, x3);
            }
        }
    }
}

// ---- fp32 -> fp16 round copy ----
__global__ void __launch_bounds__(256) f32_to_h(const float* __restrict__ in,
                                                __half* __restrict__ out) {
    size_t i = (size_t)blockIdx.x * blockDim.x + threadIdx.x;
    float4 v = ((const float4*)in)[i];
    __half2 h0 = __floats2half2_rn(v.x, v.y);
    __half2 h1 = __floats2half2_rn(v.z, v.w);
    ((__half2*)out)[2 * i]     = h0;
    ((__half2*)out)[2 * i + 1] = h1;
}

// ---- transpose fp32 -> half: out[c][r] = h(in[r][c]) ----
__global__ void __launch_bounds__(256) transpose_f2h(
    const float* __restrict__ in, __half* __restrict__ out, int rows, int cols)
{
    __shared__ float tbuf[32][33];
    int c0 = blockIdx.x * 32, r0 = blockIdx.y * 32;
    int x = threadIdx.x & 31, y = threadIdx.x >> 5;
#pragma unroll
    for (int i = 0; i < 32; i += 8)
        tbuf[y + i][x] = in[(size_t)(r0 + y + i) * cols + c0 + x];
    __syncthreads();
#pragma unroll
    for (int i = 0; i < 32; i += 8)
        out[(size_t)(c0 + y + i) * rows + r0 + x] = __float2half_rn(tbuf[x][y + i]);
}

// ---- transpose half -> half: out[c][r] = in[r][c] ----
__global__ void __launch_bounds__(256) transpose_h2h(
    const __half* __restrict__ in, __half* __restrict__ out,
    int rows, int cols, long long sIn, long long sOut)
{
    __shared__ __half tbuf[32][34];
    in  += (long long)blockIdx.z * sIn;
    out += (long long)blockIdx.z * sOut;
    int c0 = blockIdx.x * 32, r0 = blockIdx.y * 32;
    int x = threadIdx.x & 31, y = threadIdx.x >> 5;
#pragma unroll
    for (int i = 0; i < 32; i += 8)
        tbuf[y + i][x] = in[(size_t)(r0 + y + i) * cols + c0 + x];
    __syncthreads();
#pragma unroll
    for (int i = 0; i < 32; i += 8)
        out[(size_t)(c0 + y + i) * rows + r0 + x] = tbuf[x][y + i];
}

// ---- row softmax: fp32 logits in, fp16 weights out (2048 cols/row) ----
__global__ void __launch_bounds__(256) softmax_rows(const float* __restrict__ L,
                                                    __half* __restrict__ W) {
    const float* r = L + (size_t)blockIdx.x * 2048;
    __half* w = W + (size_t)blockIdx.x * 2048;
    const int tid = threadIdx.x, lane = tid & 31, wid = tid >> 5;
    __shared__ float red[8];

    float4 a = *(const float4*)(r + tid * 4);
    float4 b = *(const float4*)(r + 1024 + tid * 4);

    float m = fmaxf(fmaxf(fmaxf(a.x, a.y), fmaxf(a.z, a.w)),
                    fmaxf(fmaxf(b.x, b.y), fmaxf(b.z, b.w)));
#pragma unroll
    for (int o = 16; o; o >>= 1) m = fmaxf(m, __shfl_xor_sync(~0u, m, o));
    if (lane == 0) red[wid] = m;
    __syncthreads();
    m = red[0];
#pragma unroll
    for (int i = 1; i < 8; i++) m = fmaxf(m, red[i]);
    __syncthreads();

    a.x = expf(a.x - m); a.y = expf(a.y - m); a.z = expf(a.z - m); a.w = expf(a.w - m);
    b.x = expf(b.x - m); b.y = expf(b.y - m); b.z = expf(b.z - m); b.w = expf(b.w - m);
    float s = a.x + a.y + a.z + a.w + b.x + b.y + b.z + b.w;
#pragma unroll
    for (int o = 16; o; o >>= 1) s += __shfl_xor_sync(~0u, s, o);
    if (lane == 0) red[wid] = s;
    __syncthreads();
    s = red[0];
#pragma unroll
    for (int i = 1; i < 8; i++) s += red[i];
    float inv = 1.0f / s;

    *(__half2*)(w + tid * 4)            = __floats2half2_rn(a.x * inv, a.y * inv);
    *(__half2*)(w + tid * 4 + 2)        = __floats2half2_rn(a.z * inv, a.w * inv);
    *(__half2*)(w + 1024 + tid * 4)     = __floats2half2_rn(b.x * inv, b.y * inv);
    *(__half2*)(w + 1024 + tid * 4 + 2) = __floats2half2_rn(b.z * inv, b.w * inv);
}

// ---- host launcher ----
extern "C" void kernel_launch(void* const* d_in, const int* in_sizes, int n_in,
                              void* d_out, int out_size) {
    const float* q  = (const float*)d_in[0];
    const float* k  = (const float*)d_in[1];
    const float* v  = (const float*)d_in[2];
    const float* Wq = (const float*)d_in[3];
    const float* bq = (const float*)d_in[4];
    float* out = (float*)d_out;

    __half *pX, *pP, *pWt, *pVT, *pWT;
    float  *pL;
    cudaGetSymbolAddress((void**)&pX,  g_Xh);
    cudaGetSymbolAddress((void**)&pP,  g_Ph);
    cudaGetSymbolAddress((void**)&pL,  g_L);
    cudaGetSymbolAddress((void**)&pWt, g_Wt);
    cudaGetSymbolAddress((void**)&pVT, g_VTh);
    cudaGetSymbolAddress((void**)&pWT, g_WTh);

    cudaFuncSetAttribute(gemm_fp16, cudaFuncAttributeMaxDynamicSharedMemorySize, GSMEM_BYTES);

    // 1) round inputs to fp16
    f32_to_h<<<16384, 256>>>(q, pX);
    f32_to_h<<<16384, 256>>>(k, pX + NELEM);
    f32_to_h<<<16384, 256>>>(v, pX + 2 * NELEM);
    // 2) W^T (K-major B operand), half
    transpose_f2h<<<dim3(32, 32, 1), 256>>>(Wq, pWT, D_, D_);
    // 3) fused projections: [3*16384,1024] = X @ W + b -> half P
    gemm_fp16<<<dim3(384, 8, 1), 256, GSMEM_BYTES>>>(
        pX, pWT, nullptr, pP, bq, 1.0f, D_, D_, 0, 0, 0);
    // 4) logits = Q @ K^T / 32 -> fp32 L
    gemm_fp16<<<dim3(16, 16, 8), 256, GSMEM_BYTES>>>(
        pP, pP + NELEM, pL, nullptr, nullptr, 0.03125f, D_, S_, SB_, SB_, SL_);
    // 5) softmax rows -> half weights
    softmax_rows<<<B_ * S_, 256>>>(pL, pWt);
    // 6) V^T per batch (half)
    transpose_h2h<<<dim3(32, 64, 8), 256>>>(pP + 2 * NELEM, pVT, S_, D_, SB_, SB_);
    // 7) out = weights @ V -> fp32
    gemm_fp16<<<dim3(16, 8, 8), 256, GSMEM_BYTES>>>(
        pWt, pVT, out, nullptr, nullptr, 1.0f, S_, D_, SL_, SB_, SB_);
}

// round 12
// speedup vs baseline: 2.0798x; 1.0789x over previous
#include <cuda_runtime.h>
#include <cuda_fp16.h>
#include <cstdint>
#include <cstddef>

#define B_ 8
#define S_ 2048
#define D_ 1024
#define MTOK (B_ * S_)
#define NELEM ((size_t)MTOK * D_)
#define SB_ ((long long)S_ * D_)
#define SL_ ((long long)S_ * S_)

// ---- static device scratch (allocation-free rule) ----
__device__ __align__(16) __half g_Xh[3 * NELEM];             // fp16-rounded inputs
__device__ __align__(16) __half g_Ph[3 * NELEM];             // projected Q,K,V (half)
__device__ __align__(16) float  g_L[(size_t)B_ * S_ * S_];   // fp32 logits
__device__ __align__(16) __half g_Wt[(size_t)B_ * S_ * S_];  // softmax weights (half)
__device__ __align__(16) __half g_VTh[(size_t)B_ * D_ * S_]; // V^T per batch (half)
__device__ __align__(16) __half g_WTh[(size_t)D_ * D_];      // W^T (half)

// ---- helpers ----
__device__ __forceinline__ uint32_t smem_u32(const void* p) {
    uint32_t a;
    asm("{ .reg .u64 t; cvta.to.shared.u64 t, %1; cvt.u32.u64 %0, t; }" : "=r"(a) : "l"(p));
    return a;
}
__device__ __forceinline__ void cp16(uint32_t s, const void* g) {
    asm volatile("cp.async.cg.shared.global [%0], [%1], 16;" :: "r"(s), "l"(g) : "memory");
}
__device__ __forceinline__ void mma_f16(float* c, const uint32_t* a, const uint32_t* b) {
    asm volatile(
        "mma.sync.aligned.m16n8k16.row.col.f32.f16.f16.f32 "
        "{%0,%1,%2,%3}, {%4,%5,%6,%7}, {%8,%9}, {%0,%1,%2,%3};"
        : "+f"(c[0]), "+f"(c[1]), "+f"(c[2]), "+f"(c[3])
        : "r"(a[0]), "r"(a[1]), "r"(a[2]), "r"(a[3]), "r"(b[0]), "r"(b[1]));
}
__device__ __forceinline__ void ldsm_x4(uint32_t* r, uint32_t addr) {
    asm volatile("ldmatrix.sync.aligned.m8n8.x4.shared.b16 {%0,%1,%2,%3}, [%4];"
                 : "=r"(r[0]), "=r"(r[1]), "=r"(r[2]), "=r"(r[3]) : "r"(addr));
}

// ---- fp16 GEMM (fp32 accum): C = scale*(A[M,K] @ B[N,K]^T) (+bias) ----
// CTA tile 128x128, BK=64 halves, 8 warps as 4Mx2N (warp 32x64),
// 3-stage cp.async pipeline, ldmatrix fragment loads.
#define BKH 64
#define LDH 72                         // 64 + 8 pad halves (16B-aligned rows)
#define ASTGH (128 * LDH)              // 9216 halves per operand stage
#define STGH (2 * ASTGH)
#define GSMEM_BYTES (512 + 3 * STGH * 2)   // ~111 KB

__device__ __forceinline__ void load_tile_h(const __half* __restrict__ src, int ld,
                                            int row0, int k0, __half* st, int tid) {
#pragma unroll
    for (int i = 0; i < 4; i++) {              // 1024 chunks of 16B (8 halves)
        int idx = i * 256 + tid;
        int r = idx >> 3, c = idx & 7;
        cp16(smem_u32(st + r * LDH + c * 8),
             src + (size_t)(row0 + r) * ld + (k0 + c * 8));
    }
}

__global__ void __launch_bounds__(256, 2) gemm_fp16(
    const __half* __restrict__ A, const __half* __restrict__ Bm,
    float* __restrict__ Cf, __half* __restrict__ Ch,
    const float* __restrict__ bias,
    float scale, int K, int N,
    long long sA, long long sB, long long sC)
{
    extern __shared__ char smraw[];
    float*  bias_s = (float*)smraw;                 // 128 floats
    __half* tiles  = (__half*)(smraw + 512);

    const int tid = threadIdx.x, wid = tid >> 5, lane = tid & 31;
    const int g = lane >> 2, t = lane & 3;
    const int wm = (wid & 3) * 32;
    const int wn = (wid >> 2) * 64;
    const int m0 = blockIdx.x * 128, n0 = blockIdx.y * 128;

    A  += (long long)blockIdx.z * sA;
    Bm += (long long)blockIdx.z * sB;
    if (Cf) Cf += (long long)blockIdx.z * sC;
    if (Ch) Ch += (long long)blockIdx.z * sC;

    if (bias && tid < 128) bias_s[tid] = bias[n0 + tid];

    // ldmatrix per-lane row decode (byte offsets within a stage)
    const int q8 = lane >> 3, r8 = lane & 7;
    // A x4: mats in order (rowhalf0,k0-7)(rowhalf1,k0-7)(rowhalf0,k8-15)(rowhalf1,k8-15)
    uint32_t aOff[2], bOff[4];
#pragma unroll
    for (int mi = 0; mi < 2; mi++)
        aOff[mi] = (uint32_t)(((wm + mi * 16 + (q8 & 1) * 8 + r8) * LDH + (q8 >> 1) * 8) * 2);
    // B x4 (nj pair p): mats (nj=2p,k0-7)(nj=2p,k8-15)(nj=2p+1,k0-7)(nj=2p+1,k8-15)
#pragma unroll
    for (int p = 0; p < 4; p++)
        bOff[p] = (uint32_t)(((wn + p * 16 + (q8 >> 1) * 8 + r8) * LDH + (q8 & 1) * 8) * 2);

    const uint32_t tilesB = smem_u32(tiles);
    const int nK = K >> 6;

#pragma unroll
    for (int p = 0; p < 2; p++) {
        load_tile_h(A,  K, m0, p * BKH, tiles + p * STGH, tid);
        load_tile_h(Bm, K, n0, p * BKH, tiles + p * STGH + ASTGH, tid);
        asm volatile("cp.async.commit_group;" ::: "memory");
    }

    float acc[2][8][4];
#pragma unroll
    for (int mi = 0; mi < 2; mi++)
#pragma unroll
        for (int nj = 0; nj < 8; nj++)
#pragma unroll
            for (int qq = 0; qq < 4; qq++) acc[mi][nj][qq] = 0.0f;

    for (int s = 0; s < nK; s++) {
        __syncthreads();
        if (s + 2 < nK) {
            __half* st = tiles + ((s + 2) % 3) * STGH;
            load_tile_h(A,  K, m0, (s + 2) * BKH, st, tid);
            load_tile_h(Bm, K, n0, (s + 2) * BKH, st + ASTGH, tid);
        }
        asm volatile("cp.async.commit_group;" ::: "memory");
        asm volatile("cp.async.wait_group 2;" ::: "memory");
        __syncthreads();

        const uint32_t AsB = tilesB + (uint32_t)((s % 3) * STGH * 2);
        const uint32_t BsB = AsB + (uint32_t)(ASTGH * 2);

#pragma unroll
        for (int ks = 0; ks < 4; ks++) {       // 4 x k16 per 64-half stage
            const uint32_t kbB = (uint32_t)(ks * 16 * 2);
            uint32_t a[2][4], b[4][4];         // b[p] = {b[2p][0],b[2p][1],b[2p+1][0],b[2p+1][1]}
#pragma unroll
            for (int mi = 0; mi < 2; mi++)
                ldsm_x4(a[mi], AsB + aOff[mi] + kbB);
#pragma unroll
            for (int p = 0; p < 4; p++)
                ldsm_x4(b[p], BsB + bOff[p] + kbB);
#pragma unroll
            for (int mi = 0; mi < 2; mi++)
#pragma unroll
                for (int p = 0; p < 4; p++) {
                    mma_f16(acc[mi][2 * p],     a[mi], &b[p][0]);
                    mma_f16(acc[mi][2 * p + 1], a[mi], &b[p][2]);
                }
        }
    }

    __syncthreads();
    const bool hb = (bias != nullptr);
#pragma unroll
    for (int mi = 0; mi < 2; mi++) {
#pragma unroll
        for (int nj = 0; nj < 8; nj++) {
            int row = m0 + wm + mi * 16 + g;
            int col = n0 + wn + nj * 8 + 2 * t;
            float b0 = hb ? bias_s[wn + nj * 8 + 2 * t]     : 0.0f;
            float b1 = hb ? bias_s[wn + nj * 8 + 2 * t + 1] : 0.0f;
            float x0 = acc[mi][nj][0] * scale + b0;
            float x1 = acc[mi][nj][1] * scale + b1;
            float x2 = acc[mi][nj][2] * scale + b0;
            float x3 = acc[mi][nj][3] * scale + b1;
            if (Ch) {
                *(__half2*)(Ch + (size_t)row * N + col)       = __floats2half2_rn(x0, x1);
                *(__half2*)(Ch + (size_t)(row + 8) * N + col) = __floats2half2_rn(x2, x3);
            } else {
                *(float2*)(Cf + (size_t)row * N + col)       = make_float2(x0, x1);
                *(float2*)(Cf + (size_t)(row + 8) * N + col) = make_float2(x2, x3);
            }
        }
    }
}

// ---- fp32 -> fp16 round copy ----
__global__ void __launch_bounds__(256) f32_to_h(const float* __restrict__ in,
                                                __half* __restrict__ out) {
    size_t i = (size_t)blockIdx.x * blockDim.x + threadIdx.x;
    float4 v = ((const float4*)in)[i];
    __half2 h0 = __floats2half2_rn(v.x, v.y);
    __half2 h1 = __floats2half2_rn(v.z, v.w);
    ((__half2*)out)[2 * i]     = h0;
    ((__half2*)out)[2 * i + 1] = h1;
}

// ---- transpose fp32 -> half: out[c][r] = h(in[r][c]) ----
__global__ void __launch_bounds__(256) transpose_f2h(
    const float* __restrict__ in, __half* __restrict__ out, int rows, int cols)
{
    __shared__ float tbuf[32][33];
    int c0 = blockIdx.x * 32, r0 = blockIdx.y * 32;
    int x = threadIdx.x & 31, y = threadIdx.x >> 5;
#pragma unroll
    for (int i = 0; i < 32; i += 8)
        tbuf[y + i][x] = in[(size_t)(r0 + y + i) * cols + c0 + x];
    __syncthreads();
#pragma unroll
    for (int i = 0; i < 32; i += 8)
        out[(size_t)(c0 + y + i) * rows + r0 + x] = __float2half_rn(tbuf[x][y + i]);
}

// ---- transpose half -> half: out[c][r] = in[r][c] ----
__global__ void __launch_bounds__(256) transpose_h2h(
    const __half* __restrict__ in, __half* __restrict__ out,
    int rows, int cols, long long sIn, long long sOut)
{
    __shared__ __half tbuf[32][34];
    in  += (long long)blockIdx.z * sIn;
    out += (long long)blockIdx.z * sOut;
    int c0 = blockIdx.x * 32, r0 = blockIdx.y * 32;
    int x = threadIdx.x & 31, y = threadIdx.x >> 5;
#pragma unroll
    for (int i = 0; i < 32; i += 8)
        tbuf[y + i][x] = in[(size_t)(r0 + y + i) * cols + c0 + x];
    __syncthreads();
#pragma unroll
    for (int i = 0; i < 32; i += 8)
        out[(size_t)(c0 + y + i) * rows + r0 + x] = tbuf[x][y + i];
}

// ---- row softmax: fp32 logits in, fp16 weights out (2048 cols/row) ----
__global__ void __launch_bounds__(256) softmax_rows(const float* __restrict__ L,
                                                    __half* __restrict__ W) {
    const float* r = L + (size_t)blockIdx.x * 2048;
    __half* w = W + (size_t)blockIdx.x * 2048;
    const int tid = threadIdx.x, lane = tid & 31, wid = tid >> 5;
    __shared__ float red[8];

    float4 a = *(const float4*)(r + tid * 4);
    float4 b = *(const float4*)(r + 1024 + tid * 4);

    float m = fmaxf(fmaxf(fmaxf(a.x, a.y), fmaxf(a.z, a.w)),
                    fmaxf(fmaxf(b.x, b.y), fmaxf(b.z, b.w)));
#pragma unroll
    for (int o = 16; o; o >>= 1) m = fmaxf(m, __shfl_xor_sync(~0u, m, o));
    if (lane == 0) red[wid] = m;
    __syncthreads();
    m = red[0];
#pragma unroll
    for (int i = 1; i < 8; i++) m = fmaxf(m, red[i]);
    __syncthreads();

    a.x = expf(a.x - m); a.y = expf(a.y - m); a.z = expf(a.z - m); a.w = expf(a.w - m);
    b.x = expf(b.x - m); b.y = expf(b.y - m); b.z = expf(b.z - m); b.w = expf(b.w - m);
    float s = a.x + a.y + a.z + a.w + b.x + b.y + b.z + b.w;
#pragma unroll
    for (int o = 16; o; o >>= 1) s += __shfl_xor_sync(~0u, s, o);
    if (lane == 0) red[wid] = s;
    __syncthreads();
    s = red[0];
#pragma unroll
    for (int i = 1; i < 8; i++) s += red[i];
    float inv = 1.0f / s;

    *(__half2*)(w + tid * 4)            = __floats2half2_rn(a.x * inv, a.y * inv);
    *(__half2*)(w + tid * 4 + 2)        = __floats2half2_rn(a.z * inv, a.w * inv);
    *(__half2*)(w + 1024 + tid * 4)     = __floats2half2_rn(b.x * inv, b.y * inv);
    *(__half2*)(w + 1024 + tid * 4 + 2) = __floats2half2_rn(b.z * inv, b.w * inv);
}

// ---- host launcher ----
extern "C" void kernel_launch(void* const* d_in, const int* in_sizes, int n_in,
                              void* d_out, int out_size) {
    const float* q  = (const float*)d_in[0];
    const float* k  = (const float*)d_in[1];
    const float* v  = (const float*)d_in[2];
    const float* Wq = (const float*)d_in[3];
    const float* bq = (const float*)d_in[4];
    float* out = (float*)d_out;

    __half *pX, *pP, *pWt, *pVT, *pWT;
    float  *pL;
    cudaGetSymbolAddress((void**)&pX,  g_Xh);
    cudaGetSymbolAddress((void**)&pP,  g_Ph);
    cudaGetSymbolAddress((void**)&pL,  g_L);
    cudaGetSymbolAddress((void**)&pWt, g_Wt);
    cudaGetSymbolAddress((void**)&pVT, g_VTh);
    cudaGetSymbolAddress((void**)&pWT, g_WTh);

    cudaFuncSetAttribute(gemm_fp16, cudaFuncAttributeMaxDynamicSharedMemorySize, GSMEM_BYTES);

    // 1) round inputs to fp16
    f32_to_h<<<16384, 256>>>(q, pX);
    f32_to_h<<<16384, 256>>>(k, pX + NELEM);
    f32_to_h<<<16384, 256>>>(v, pX + 2 * NELEM);
    // 2) W^T (K-major B operand), half
    transpose_f2h<<<dim3(32, 32, 1), 256>>>(Wq, pWT, D_, D_);
    // 3) fused projections: [3*16384,1024] = X @ W + b -> half P
    gemm_fp16<<<dim3(384, 8, 1), 256, GSMEM_BYTES>>>(
        pX, pWT, nullptr, pP, bq, 1.0f, D_, D_, 0, 0, 0);
    // 4) logits = Q @ K^T / 32 -> fp32 L
    gemm_fp16<<<dim3(16, 16, 8), 256, GSMEM_BYTES>>>(
        pP, pP + NELEM, pL, nullptr, nullptr, 0.03125f, D_, S_, SB_, SB_, SL_);
    // 5) softmax rows -> half weights
    softmax_rows<<<B_ * S_, 256>>>(pL, pWt);
    // 6) V^T per batch (half)
    transpose_h2h<<<dim3(32, 64, 8), 256>>>(pP + 2 * NELEM, pVT, S_, D_, SB_, SB_);
    // 7) out = weights @ V -> fp32
    gemm_fp16<<<dim3(16, 8, 8), 256, GSMEM_BYTES>>>(
        pWt, pVT, out, nullptr, nullptr, 1.0f, S_, D_, SL_, SB_, SB_);
}

// round 16
// speedup vs baseline: 2.1008x; 1.0101x over previous
#include <cuda_runtime.h>
#include <cuda_fp16.h>
#include <cstdint>
#include <cstddef>

#define B_ 8
#define S_ 2048
#define D_ 1024
#define MTOK (B_ * S_)
#define NELEM ((size_t)MTOK * D_)
#define SB_ ((long long)S_ * D_)
#define SL_ ((long long)S_ * S_)

// ---- static device scratch (allocation-free rule) ----
__device__ __align__(16) __half g_Xh[3 * NELEM];             // fp16-rounded inputs
__device__ __align__(16) __half g_Ph[3 * NELEM];             // projected Q,K,V (half)
__device__ __align__(16) float  g_L[(size_t)B_ * S_ * S_];   // fp32 logits
__device__ __align__(16) __half g_Wt[(size_t)B_ * S_ * S_];  // softmax weights (half)
__device__ __align__(16) __half g_WTh[(size_t)D_ * D_];      // W^T (half)

// ---- helpers ----
__device__ __forceinline__ uint32_t smem_u32(const void* p) {
    uint32_t a;
    asm("{ .reg .u64 t; cvta.to.shared.u64 t, %1; cvt.u32.u64 %0, t; }" : "=r"(a) : "l"(p));
    return a;
}
__device__ __forceinline__ void cp16(uint32_t s, const void* g) {
    asm volatile("cp.async.cg.shared.global [%0], [%1], 16;" :: "r"(s), "l"(g) : "memory");
}
__device__ __forceinline__ void mma_f16(float* c, const uint32_t* a, const uint32_t* b) {
    asm volatile(
        "mma.sync.aligned.m16n8k16.row.col.f32.f16.f16.f32 "
        "{%0,%1,%2,%3}, {%4,%5,%6,%7}, {%8,%9}, {%0,%1,%2,%3};"
        : "+f"(c[0]), "+f"(c[1]), "+f"(c[2]), "+f"(c[3])
        : "r"(a[0]), "r"(a[1]), "r"(a[2]), "r"(a[3]), "r"(b[0]), "r"(b[1]));
}
__device__ __forceinline__ void ldsm_x4(uint32_t* r, uint32_t addr) {
    asm volatile("ldmatrix.sync.aligned.m8n8.x4.shared.b16 {%0,%1,%2,%3}, [%4];"
                 : "=r"(r[0]), "=r"(r[1]), "=r"(r[2]), "=r"(r[3]) : "r"(addr));
}
__device__ __forceinline__ void ldsm_x4_t(uint32_t* r, uint32_t addr) {
    asm volatile("ldmatrix.sync.aligned.m8n8.x4.trans.shared.b16 {%0,%1,%2,%3}, [%4];"
                 : "=r"(r[0]), "=r"(r[1]), "=r"(r[2]), "=r"(r[3]) : "r"(addr));
}

// ---- fp16 GEMM (fp32 accum): C = scale*(A[M,K] @ Bop) (+bias) ----
// BT=0: B is [N,K] K-major (Bop = B^T).  BT=1: B is [K,N] row-major (Bop = B).
// CTA tile 128x128, BK=64, 8 warps 4Mx2N (warp 32x64), 3-stage cp.async, ldmatrix.
#define BKH 64
#define LDH 72                          // A rows: 64 + 8 pad halves
#define ASTGH (128 * LDH)               // 9216 halves
#define LDBT 136                        // BT=1 B rows: 128 + 8 pad halves
#define BSTGH0 (128 * LDH)              // 9216
#define BSTGH1 (BKH * LDBT)             // 8704
#define STGH0 (ASTGH + BSTGH0)
#define STGH1 (ASTGH + BSTGH1)
#define GSMEM0 (512 + 3 * STGH0 * 2)    // ~111 KB
#define GSMEM1 (512 + 3 * STGH1 * 2)    // ~108 KB

__device__ __forceinline__ void load_tile_a(const __half* __restrict__ src, int ld,
                                            int row0, int k0, __half* st, int tid) {
#pragma unroll
    for (int i = 0; i < 4; i++) {               // 1024 chunks of 16B
        int idx = i * 256 + tid;
        int r = idx >> 3, c = idx & 7;
        cp16(smem_u32(st + r * LDH + c * 8),
             src + (size_t)(row0 + r) * ld + (k0 + c * 8));
    }
}
__device__ __forceinline__ void load_tile_bt(const __half* __restrict__ src, int ld,
                                             int k0, int n0, __half* st, int tid) {
#pragma unroll
    for (int i = 0; i < 4; i++) {               // 64 rows x 16 chunks of 16B
        int idx = i * 256 + tid;
        int r = idx >> 4, c = idx & 15;
        cp16(smem_u32(st + r * LDBT + c * 8),
             src + (size_t)(k0 + r) * ld + (n0 + c * 8));
    }
}

template <int BT>
__global__ void __launch_bounds__(256, 2) gemm_fp16(
    const __half* __restrict__ A, const __half* __restrict__ Bm,
    float* __restrict__ Cf, __half* __restrict__ Ch,
    const float* __restrict__ bias,
    float scale, int K, int N, int ldb,
    long long sA, long long sB, long long sC)
{
    extern __shared__ char smraw[];
    float*  bias_s = (float*)smraw;
    __half* tiles  = (__half*)(smraw + 512);

    const int STGH  = BT ? STGH1 : STGH0;

    const int tid = threadIdx.x, wid = tid >> 5, lane = tid & 31;
    const int g = lane >> 2, t = lane & 3;
    const int wm = (wid & 3) * 32;
    const int wn = (wid >> 2) * 64;
    const int m0 = blockIdx.x * 128, n0 = blockIdx.y * 128;

    A  += (long long)blockIdx.z * sA;
    Bm += (long long)blockIdx.z * sB;
    if (Cf) Cf += (long long)blockIdx.z * sC;
    if (Ch) Ch += (long long)blockIdx.z * sC;

    if (bias && tid < 128) bias_s[tid] = bias[n0 + tid];

    const int q8 = lane >> 3, r8 = lane & 7;
    uint32_t aOff[2], bOff[4];
#pragma unroll
    for (int mi = 0; mi < 2; mi++)
        aOff[mi] = (uint32_t)(((wm + mi * 16 + (q8 & 1) * 8 + r8) * LDH + (q8 >> 1) * 8) * 2);
    if (BT) {
        // B [k,n]: mats (k0-7,n0-7)(k8-15,n0-7)(k0-7,n8-15)(k8-15,n8-15), trans
#pragma unroll
        for (int p = 0; p < 4; p++)
            bOff[p] = (uint32_t)((((q8 & 1) * 8 + r8) * LDBT + wn + p * 16 + (q8 >> 1) * 8) * 2);
    } else {
        // B [n,k] K-major: mats (n0-7,k0-7)(n0-7,k8-15)(n8-15,k0-7)(n8-15,k8-15)
#pragma unroll
        for (int p = 0; p < 4; p++)
            bOff[p] = (uint32_t)(((wn + p * 16 + (q8 >> 1) * 8 + r8) * LDH + (q8 & 1) * 8) * 2);
    }

    const uint32_t tilesB = smem_u32(tiles);
    const int nK = K >> 6;

#pragma unroll
    for (int p = 0; p < 2; p++) {
        load_tile_a(A, K, m0, p * BKH, tiles + p * STGH, tid);
        if (BT) load_tile_bt(Bm, ldb, p * BKH, n0, tiles + p * STGH + ASTGH, tid);
        else    load_tile_a(Bm, ldb, n0, p * BKH, tiles + p * STGH + ASTGH, tid);
        asm volatile("cp.async.commit_group;" ::: "memory");
    }

    float acc[2][8][4];
#pragma unroll
    for (int mi = 0; mi < 2; mi++)
#pragma unroll
        for (int nj = 0; nj < 8; nj++)
#pragma unroll
            for (int qq = 0; qq < 4; qq++) acc[mi][nj][qq] = 0.0f;

    for (int s = 0; s < nK; s++) {
        __syncthreads();
        if (s + 2 < nK) {
            __half* st = tiles + ((s + 2) % 3) * STGH;
            load_tile_a(A, K, m0, (s + 2) * BKH, st, tid);
            if (BT) load_tile_bt(Bm, ldb, (s + 2) * BKH, n0, st + ASTGH, tid);
            else    load_tile_a(Bm, ldb, n0, (s + 2) * BKH, st + ASTGH, tid);
        }
        asm volatile("cp.async.commit_group;" ::: "memory");
        asm volatile("cp.async.wait_group 2;" ::: "memory");
        __syncthreads();

        const uint32_t AsB = tilesB + (uint32_t)((s % 3) * STGH * 2);
        const uint32_t BsB = AsB + (uint32_t)(ASTGH * 2);

#pragma unroll
        for (int ks = 0; ks < 4; ks++) {
            const uint32_t kaB = (uint32_t)(ks * 32);                 // 16 halves
            const uint32_t kbB = BT ? (uint32_t)(ks * 16 * LDBT * 2)  // 16 k-rows
                                    : (uint32_t)(ks * 32);
            uint32_t a[2][4], b[4][4];
#pragma unroll
            for (int mi = 0; mi < 2; mi++)
                ldsm_x4(a[mi], AsB + aOff[mi] + kaB);
#pragma unroll
            for (int p = 0; p < 4; p++) {
                if (BT) ldsm_x4_t(b[p], BsB + bOff[p] + kbB);
                else    ldsm_x4(b[p], BsB + bOff[p] + kbB);
            }
#pragma unroll
            for (int mi = 0; mi < 2; mi++)
#pragma unroll
                for (int p = 0; p < 4; p++) {
                    mma_f16(acc[mi][2 * p],     a[mi], &b[p][0]);
                    mma_f16(acc[mi][2 * p + 1], a[mi], &b[p][2]);
                }
        }
    }

    __syncthreads();
    const bool hb = (bias != nullptr);
#pragma unroll
    for (int mi = 0; mi < 2; mi++) {
#pragma unroll
        for (int nj = 0; nj < 8; nj++) {
            int row = m0 + wm + mi * 16 + g;
            int col = n0 + wn + nj * 8 + 2 * t;
            float b0 = hb ? bias_s[wn + nj * 8 + 2 * t]     : 0.0f;
            float b1 = hb ? bias_s[wn + nj * 8 + 2 * t + 1] : 0.0f;
            float x0 = acc[mi][nj][0] * scale + b0;
            float x1 = acc[mi][nj][1] * scale + b1;
            float x2 = acc[mi][nj][2] * scale + b0;
            float x3 = acc[mi][nj][3] * scale + b1;
            if (Ch) {
                *(__half2*)(Ch + (size_t)row * N + col)       = __floats2half2_rn(x0, x1);
                *(__half2*)(Ch + (size_t)(row + 8) * N + col) = __floats2half2_rn(x2, x3);
            } else {
                *(float2*)(Cf + (size_t)row * N + col)       = make_float2(x0, x1);
                *(float2*)(Cf + (size_t)(row + 8) * N + col) = make_float2(x2, x3);
            }
        }
    }
}

// ---- fp32 -> fp16 round copy ----
__global__ void __launch_bounds__(256) f32_to_h(const float* __restrict__ in,
                                                __half* __restrict__ out) {
    size_t i = (size_t)blockIdx.x * blockDim.x + threadIdx.x;
    float4 v = ((const float4*)in)[i];
    ((__half2*)out)[2 * i]     = __floats2half2_rn(v.x, v.y);
    ((__half2*)out)[2 * i + 1] = __floats2half2_rn(v.z, v.w);
}

// ---- transpose fp32 -> half: out[c][r] = h(in[r][c]) ----
__global__ void __launch_bounds__(256) transpose_f2h(
    const float* __restrict__ in, __half* __restrict__ out, int rows, int cols)
{
    __shared__ float tbuf[32][33];
    int c0 = blockIdx.x * 32, r0 = blockIdx.y * 32;
    int x = threadIdx.x & 31, y = threadIdx.x >> 5;
#pragma unroll
    for (int i = 0; i < 32; i += 8)
        tbuf[y + i][x] = in[(size_t)(r0 + y + i) * cols + c0 + x];
    __syncthreads();
#pragma unroll
    for (int i = 0; i < 32; i += 8)
        out[(size_t)(c0 + y + i) * rows + r0 + x] = __float2half_rn(tbuf[x][y + i]);
}

// ---- row softmax: fp32 logits in, fp16 weights out (2048 cols/row) ----
__global__ void __launch_bounds__(256) softmax_rows(const float* __restrict__ L,
                                                    __half* __restrict__ W) {
    const float* r = L + (size_t)blockIdx.x * 2048;
    __half* w = W + (size_t)blockIdx.x * 2048;
    const int tid = threadIdx.x, lane = tid & 31, wid = tid >> 5;
    __shared__ float red[8];

    float4 a = *(const float4*)(r + tid * 4);
    float4 b = *(const float4*)(r + 1024 + tid * 4);

    float m = fmaxf(fmaxf(fmaxf(a.x, a.y), fmaxf(a.z, a.w)),
                    fmaxf(fmaxf(b.x, b.y), fmaxf(b.z, b.w)));
#pragma unroll
    for (int o = 16; o; o >>= 1) m = fmaxf(m, __shfl_xor_sync(~0u, m, o));
    if (lane == 0) red[wid] = m;
    __syncthreads();
    m = red[0];
#pragma unroll
    for (int i = 1; i < 8; i++) m = fmaxf(m, red[i]);
    __syncthreads();

    a.x = expf(a.x - m); a.y = expf(a.y - m); a.z = expf(a.z - m); a.w = expf(a.w - m);
    b.x = expf(b.x - m); b.y = expf(b.y - m); b.z = expf(b.z - m); b.w = expf(b.w - m);
    float s = a.x + a.y + a.z + a.w + b.x + b.y + b.z + b.w;
#pragma unroll
    for (int o = 16; o; o >>= 1) s += __shfl_xor_sync(~0u, s, o);
    if (lane == 0) red[wid] = s;
    __syncthreads();
    s = red[0];
#pragma unroll
    for (int i = 1; i < 8; i++) s += red[i];
    float inv = 1.0f / s;

    *(__half2*)(w + tid * 4)            = __floats2half2_rn(a.x * inv, a.y * inv);
    *(__half2*)(w + tid * 4 + 2)        = __floats2half2_rn(a.z * inv, a.w * inv);
    *(__half2*)(w + 1024 + tid * 4)     = __floats2half2_rn(b.x * inv, b.y * inv);
    *(__half2*)(w + 1024 + tid * 4 + 2) = __floats2half2_rn(b.z * inv, b.w * inv);
}

// ---- host launcher ----
extern "C" void kernel_launch(void* const* d_in, const int* in_sizes, int n_in,
                              void* d_out, int out_size) {
    const float* q  = (const float*)d_in[0];
    const float* k  = (const float*)d_in[1];
    const float* v  = (const float*)d_in[2];
    const float* Wq = (const float*)d_in[3];
    const float* bq = (const float*)d_in[4];
    float* out = (float*)d_out;

    __half *pX, *pP, *pWt, *pWT;
    float  *pL;
    cudaGetSymbolAddress((void**)&pX,  g_Xh);
    cudaGetSymbolAddress((void**)&pP,  g_Ph);
    cudaGetSymbolAddress((void**)&pL,  g_L);
    cudaGetSymbolAddress((void**)&pWt, g_Wt);
    cudaGetSymbolAddress((void**)&pWT, g_WTh);

    cudaFuncSetAttribute(gemm_fp16<0>, cudaFuncAttributeMaxDynamicSharedMemorySize, GSMEM0);
    cudaFuncSetAttribute(gemm_fp16<1>, cudaFuncAttributeMaxDynamicSharedMemorySize, GSMEM1);

    // 1) round inputs to fp16
    f32_to_h<<<16384, 256>>>(q, pX);
    f32_to_h<<<16384, 256>>>(k, pX + NELEM);
    f32_to_h<<<16384, 256>>>(v, pX + 2 * NELEM);
    // 2) W^T (K-major B operand), half
    transpose_f2h<<<dim3(32, 32, 1), 256>>>(Wq, pWT, D_, D_);
    // 3) fused projections: [3*16384,1024] = X @ W + b -> half P
    gemm_fp16<0><<<dim3(384, 8, 1), 256, GSMEM0>>>(
        pX, pWT, nullptr, pP, bq, 1.0f, D_, D_, D_, 0, 0, 0);
    // 4) logits = Q @ K^T / 32 -> fp32 L  (fp16 logits failed rel-err; keep fp32)
    gemm_fp16<0><<<dim3(16, 16, 8), 256, GSMEM0>>>(
        pP, pP + NELEM, pL, nullptr, nullptr, 0.03125f, D_, S_, D_, SB_, SB_, SL_);
    // 5) softmax rows (fp32 -> half weights)
    softmax_rows<<<B_ * S_, 256>>>(pL, pWt);
    // 6) out = weights @ V  (V consumed in native [s,d] layout via ldmatrix.trans)
    gemm_fp16<1><<<dim3(16, 8, 8), 256, GSMEM1>>>(
        pWt, pP + 2 * NELEM, out, nullptr, nullptr, 1.0f, S_, D_, D_, SL_, SB_, SB_);
}